// round 6
// baseline (speedup 1.0000x reference)
#include <cuda_runtime.h>
#include <cuda_bf16.h>

// CRF forward, scaled-probability domain, f32x2-packed (2 batches per warp,
// packed into the halves of 64-bit registers), delayed-apply renormalization.
//
//   feats      : (512, 1024, 32) f32
//   mask       : (512, 1024)     f32  (0/1 semantics, handled generically)
//   transition : (32, 32)        f32
//   out        : (1024,)         f32
//
// alpha_t[j] = feat[t,b,j] + logsumexp_i(alpha_{t-1}[i] + T[j,i])
// p = exp(alpha - M), E = exp(T):   q = E p ;  p' = q * exp(feat)
// masked:  p' = p + m*(q*ef - p)   (linear in p, so uniform scaling commutes)
//
// Renorm: every 4 steps snapshot s = max_j(p) (butterfly, OFF the critical
// path), apply 1/s one period later (single packed MUL on the chain).
// Worst-case growth per step <= 32*e^{Tmax}*e^{fmax} ~ 2^14; 8-step
// unapplied span <= 2^110 < fp32 max. M += log(s) per snapshot.
//
// Mapping: warp = batches {2g, 2g+1}; lane = tag j. 512 warps = 128 blocks
// x 128 threads -> 1 warp/SMSP on 128 SMs, chain runs contention-free.

#define SEQ   512
#define BATCH 1024
#define TAGS  32
#define START_TAG 30
#define END_TAG   31
#define WPB   4
#define TPB   128
#define NBLOCKS 128

typedef unsigned long long u64;

__device__ __forceinline__ u64 pack2(float lo, float hi) {
    u64 r; asm("mov.b64 %0, {%1, %2};" : "=l"(r) : "f"(lo), "f"(hi)); return r;
}
__device__ __forceinline__ void unpack2(u64 v, float& lo, float& hi) {
    asm("mov.b64 {%0, %1}, %2;" : "=f"(lo), "=f"(hi) : "l"(v));
}
__device__ __forceinline__ u64 fma2(u64 a, u64 b, u64 c) {
    u64 r; asm("fma.rn.f32x2 %0, %1, %2, %3;" : "=l"(r) : "l"(a), "l"(b), "l"(c)); return r;
}
__device__ __forceinline__ u64 add2(u64 a, u64 b) {
    u64 r; asm("add.rn.f32x2 %0, %1, %2;" : "=l"(r) : "l"(a), "l"(b)); return r;
}
__device__ __forceinline__ u64 mul2(u64 a, u64 b) {
    u64 r; asm("mul.rn.f32x2 %0, %1, %2;" : "=l"(r) : "l"(a), "l"(b)); return r;
}

__global__ __launch_bounds__(TPB, 1)
void crf_fwd_kernel(const float* __restrict__ feats,
                    const float* __restrict__ mask,
                    const float* __restrict__ trans,
                    float* __restrict__ out)
{
    const int j  = threadIdx.x & 31;          // tag
    const int w  = threadIdx.x >> 5;          // warp in block
    const int g  = blockIdx.x * WPB + w;      // global warp id
    const int b0 = 2 * g;                     // two batches per warp
    // b1 = b0 + 1 (packed in the .hi half)

    // double-buffered packed p per warp: sp[w][buf][i] = {p_i^b0, p_i^b1}
    __shared__ __align__(16) u64 sp[WPB][2][TAGS];

    // ---- E row j, duplicated into both halves ----------------------------
    u64 e2[TAGS];
#pragma unroll
    for (int i = 0; i < TAGS; ++i) {
        const float e = __expf(trans[j * TAGS + i]);
        e2[i] = pack2(e, e);
    }
    const float eEnd = __expf(trans[END_TAG * TAGS + j]);
    const u64 NEG1_2 = pack2(-1.0f, -1.0f);

    // ---- init ------------------------------------------------------------
    const float pinit = (j == START_TAG) ? 1.0f : 0.0f;
    u64 p2 = pack2(pinit, pinit);
    float M0 = 0.0f, M1 = 0.0f;
    u64 pinv2 = pack2(1.0f, 1.0f);            // pending (delayed) scale
    sp[w][0][j] = p2;

    // ---- prefetch rings (8 steps ahead): ef2 = exp(feat), m2 = mask ------
    const int fb0 = b0 * TAGS + j;            // feat index for batch b0
    const float2* __restrict__ MK2 = reinterpret_cast<const float2*>(mask);
    const int mbase = g;                      // MK2[t*512 + g] = {m_b0, m_b1}

    u64 efr[8], mr[8];
#pragma unroll
    for (int u = 0; u < 8; ++u) {
        const float f0 = feats[u * (BATCH * TAGS) + fb0];
        const float f1 = feats[u * (BATCH * TAGS) + fb0 + TAGS];
        efr[u] = pack2(__expf(f0), __expf(f1));
        const float2 mv = MK2[u * (BATCH / 2) + mbase];
        mr[u] = pack2(mv.x, mv.y);
    }

    // ---- main recurrence -------------------------------------------------
    for (int blk = 0; blk < SEQ / 8; ++blk) {
        const int t0 = blk * 8;

#pragma unroll
        for (int u = 0; u < 8; ++u) {
            const u64 ef2 = efr[u];
            const u64 m2  = mr[u];

            // prefetch t+8 (wraps harmlessly on the final block)
            const int tp = (t0 + 8 + u) & (SEQ - 1);
            {
                const float f0 = feats[tp * (BATCH * TAGS) + fb0];
                const float f1 = feats[tp * (BATCH * TAGS) + fb0 + TAGS];
                efr[u] = pack2(__expf(f0), __expf(f1));
                const float2 mv = MK2[tp * (BATCH / 2) + mbase];
                mr[u] = pack2(mv.x, mv.y);
            }

            __syncwarp();   // previous step's STS visible

            // q2[j] = sum_i e2[i] * p2[i]  (broadcast LDS.128, 8 accums)
            const ulonglong2* __restrict__ src =
                reinterpret_cast<const ulonglong2*>(sp[w][u & 1]);
            u64 a0 = 0, a1 = 0, a2 = 0, a3 = 0, a4 = 0, a5 = 0, a6 = 0, a7 = 0;
#pragma unroll
            for (int h = 0; h < 4; ++h) {
                const ulonglong2 v0 = src[4 * h + 0];
                const ulonglong2 v1 = src[4 * h + 1];
                const ulonglong2 v2 = src[4 * h + 2];
                const ulonglong2 v3 = src[4 * h + 3];
                a0 = fma2(e2[8 * h + 0], v0.x, a0);
                a1 = fma2(e2[8 * h + 1], v0.y, a1);
                a2 = fma2(e2[8 * h + 2], v1.x, a2);
                a3 = fma2(e2[8 * h + 3], v1.y, a3);
                a4 = fma2(e2[8 * h + 4], v2.x, a4);
                a5 = fma2(e2[8 * h + 5], v2.y, a5);
                a6 = fma2(e2[8 * h + 6], v3.x, a6);
                a7 = fma2(e2[8 * h + 7], v3.y, a7);
            }
            const u64 q2 = add2(add2(add2(a0, a1), add2(a2, a3)),
                                add2(add2(a4, a5), add2(a6, a7)));

            const u64 r2 = mul2(q2, ef2);
            // p' = p + m*(r - p)   (2 packed FMAs, no unpack)
            p2 = fma2(m2, fma2(p2, NEG1_2, r2), p2);

            // ---- delayed renorm, period 4 --------------------------------
            if ((u & 3) == 3) {
                p2 = mul2(p2, pinv2);          // apply PREVIOUS scale (on chain)
                // snapshot max of current p (consumers are 4 steps away:
                // butterfly/log/rcp latency hides under the next steps)
                float sx, sy; unpack2(p2, sx, sy);
#pragma unroll
                for (int off = 16; off > 0; off >>= 1) {
                    sx = fmaxf(sx, __shfl_xor_sync(0xffffffffu, sx, off));
                    sy = fmaxf(sy, __shfl_xor_sync(0xffffffffu, sy, off));
                }
                M0 += __logf(sx);
                M1 += __logf(sy);
                pinv2 = pack2(__frcp_rn(sx), __frcp_rn(sy));
            }

            sp[w][(u + 1) & 1][j] = p2;        // publish for next step
        }
    }

    // ---- epilogue: apply final pending scale, then logsumexp -------------
    p2 = mul2(p2, pinv2);
    float px, py; unpack2(p2, px, py);
    float ax = px * eEnd;
    float ay = py * eEnd;
#pragma unroll
    for (int off = 16; off > 0; off >>= 1) {
        ax += __shfl_xor_sync(0xffffffffu, ax, off);
        ay += __shfl_xor_sync(0xffffffffu, ay, off);
    }
    if (j == 0) {
        out[b0]     = M0 + __logf(ax);
        out[b0 + 1] = M1 + __logf(ay);
    }
}

extern "C" void kernel_launch(void* const* d_in, const int* in_sizes, int n_in,
                              void* d_out, int out_size)
{
    const float* feats = (const float*)d_in[0];
    const float* msk   = (const float*)d_in[1];
    const float* trans = (const float*)d_in[2];
    float*       o     = (float*)d_out;

    crf_fwd_kernel<<<NBLOCKS, TPB>>>(feats, msk, trans, o);
}

// round 7
// speedup vs baseline: 1.1128x; 1.1128x over previous
#include <cuda_runtime.h>
#include <cuda_bf16.h>

// CRF forward, scaled-probability domain. TWO independent chains (batches)
// per warp, interleaved so each chain's smem/FMA latency hides under the
// other chain's instruction stream.
//
//   feats      : (512, 1024, 32) f32
//   mask       : (512, 1024)     f32   (0/1 semantics, handled generically)
//   transition : (32, 32)        f32
//   out        : (1024,)         f32
//
// alpha_t[j] = feat[t,b,j] + logsumexp_i(alpha_{t-1}[i] + T[j,i])
// p = exp(alpha - M), E = exp(T):  q = E p ;  p' = q*(m*ef) + p*(1-m)
// (linear in p, so uniform rescaling commutes through masking).
//
// Renorm: delayed-apply, period 4. Snapshot s = max_j(p) (butterfly, OFF
// the critical path; consumers 4 steps away), apply 1/s one period later
// (single MUL on-chain). Unapplied span = 8 steps <= 2^100 < fp32 max.
//
// SMEM: single-buffered p per chain. Within a warp the STS value depends on
// all of the step's LDS results (strict data dependence), and same-warp
// SMEM ops retire in issue order, so no __syncwarp is needed; a compiler
// memory barrier prevents reordering only.
//
// Mapping: warp g handles batches {2g, 2g+1}; lane = tag. 512 warps =
// 128 blocks x 128 threads -> exactly 1 warp per SMSP on 128 SMs.

#define SEQ   512
#define BATCH 1024
#define TAGS  32
#define START_TAG 30
#define END_TAG   31
#define WPB   4
#define TPB   128
#define NBLOCKS 128

__global__ __launch_bounds__(TPB, 1)
void crf_fwd_kernel(const float* __restrict__ feats,
                    const float* __restrict__ mask,
                    const float* __restrict__ trans,
                    float* __restrict__ out)
{
    const int j  = threadIdx.x & 31;       // tag
    const int w  = threadIdx.x >> 5;       // warp in block
    const int g  = blockIdx.x * WPB + w;   // global warp id
    const int b0 = 2 * g;                  // chain A batch; chain B = b0+1

    __shared__ __align__(16) float sp[WPB][2][TAGS];  // [warp][chain][tag]

    // ---- E row j in registers (shared by both chains) --------------------
    float e[TAGS];
#pragma unroll
    for (int i = 0; i < TAGS; ++i)
        e[i] = __expf(trans[j * TAGS + i]);
    const float eEnd = __expf(trans[END_TAG * TAGS + j]);

    // ---- init ------------------------------------------------------------
    const float pinit = (j == START_TAG) ? 1.0f : 0.0f;
    float pA = pinit, pB = pinit;
    float MA = 0.0f, MB = 0.0f;
    float invA = 1.0f, invB = 1.0f;        // pending (delayed) scales
    sp[w][0][j] = pA;
    sp[w][1][j] = pB;

    // ---- prefetch rings, 8 steps ahead -----------------------------------
    // em = mask * exp(feat), om = 1 - mask  (step tail = one FMA per chain)
    const int fbA = b0 * TAGS + j;
    const int fbB = fbA + TAGS;
    const float2* __restrict__ MK2 = reinterpret_cast<const float2*>(mask);

    float emA[8], emB[8], omA[8], omB[8];
#pragma unroll
    for (int u = 0; u < 8; ++u) {
        const float2 mv = MK2[u * (BATCH / 2) + g];
        emA[u] = mv.x * __expf(feats[u * (BATCH * TAGS) + fbA]);
        emB[u] = mv.y * __expf(feats[u * (BATCH * TAGS) + fbB]);
        omA[u] = 1.0f - mv.x;
        omB[u] = 1.0f - mv.y;
    }
    __syncwarp();   // initial stores visible before first iteration

    // ---- main recurrence -------------------------------------------------
    const float4* __restrict__ srcA = reinterpret_cast<const float4*>(sp[w][0]);
    const float4* __restrict__ srcB = reinterpret_cast<const float4*>(sp[w][1]);

    for (int blk = 0; blk < SEQ / 8; ++blk) {
        const int t0 = blk * 8;

#pragma unroll
        for (int u = 0; u < 8; ++u) {
            const float eA = emA[u], oA = omA[u];
            const float eB = emB[u], oB = omB[u];

            // prefetch t+8 (wraps harmlessly on the final block)
            const int tp = (t0 + 8 + u) & (SEQ - 1);
            {
                const float2 mv = MK2[tp * (BATCH / 2) + g];
                emA[u] = mv.x * __expf(feats[tp * (BATCH * TAGS) + fbA]);
                emB[u] = mv.y * __expf(feats[tp * (BATCH * TAGS) + fbB]);
                omA[u] = 1.0f - mv.x;
                omB[u] = 1.0f - mv.y;
            }

            // compiler barrier: keep prior STS before these LDS
            asm volatile("" ::: "memory");

            // qX[j] = sum_i e[i] * pX[i]  — broadcast LDS.128, 4 accums each,
            // the two chains' streams interleave to hide latency.
            float a0 = 0.f, a1 = 0.f, a2 = 0.f, a3 = 0.f;
            float c0 = 0.f, c1 = 0.f, c2 = 0.f, c3 = 0.f;
#pragma unroll
            for (int h = 0; h < 8; ++h) {
                const float4 vA = srcA[h];
                const float4 vB = srcB[h];
                a0 = fmaf(e[4 * h + 0], vA.x, a0);
                c0 = fmaf(e[4 * h + 0], vB.x, c0);
                a1 = fmaf(e[4 * h + 1], vA.y, a1);
                c1 = fmaf(e[4 * h + 1], vB.y, c1);
                a2 = fmaf(e[4 * h + 2], vA.z, a2);
                c2 = fmaf(e[4 * h + 2], vB.z, c2);
                a3 = fmaf(e[4 * h + 3], vA.w, a3);
                c3 = fmaf(e[4 * h + 3], vB.w, c3);
            }
            const float qA = (a0 + a1) + (a2 + a3);
            const float qB = (c0 + c1) + (c2 + c3);

            // tails: tmp = p*om computed while matvec runs (p from prev step)
            pA = fmaf(qA, eA, pA * oA);
            pB = fmaf(qB, eB, pB * oB);

            // ---- delayed renorm, period 4 --------------------------------
            if ((u & 3) == 3) {
                pA *= invA;                 // apply PREVIOUS scales (on-chain)
                pB *= invB;
                float sA = pA, sB = pB;     // snapshot max (off-chain)
#pragma unroll
                for (int off = 16; off > 0; off >>= 1) {
                    sA = fmaxf(sA, __shfl_xor_sync(0xffffffffu, sA, off));
                    sB = fmaxf(sB, __shfl_xor_sync(0xffffffffu, sB, off));
                }
                MA += __logf(sA);
                MB += __logf(sB);
                invA = __frcp_rn(sA);
                invB = __frcp_rn(sB);
            }

            sp[w][0][j] = pA;               // publish for next step
            sp[w][1][j] = pB;
        }
    }

    // ---- epilogue: apply pending scales, logsumexp over tags -------------
    pA *= invA;
    pB *= invB;
    float axA = pA * eEnd;
    float axB = pB * eEnd;
#pragma unroll
    for (int off = 16; off > 0; off >>= 1) {
        axA += __shfl_xor_sync(0xffffffffu, axA, off);
        axB += __shfl_xor_sync(0xffffffffu, axB, off);
    }
    if (j == 0) {
        out[b0]     = MA + __logf(axA);
        out[b0 + 1] = MB + __logf(axB);
    }
}

extern "C" void kernel_launch(void* const* d_in, const int* in_sizes, int n_in,
                              void* d_out, int out_size)
{
    const float* feats = (const float*)d_in[0];
    const float* msk   = (const float*)d_in[1];
    const float* trans = (const float*)d_in[2];
    float*       o     = (float*)d_out;

    crf_fwd_kernel<<<NBLOCKS, TPB>>>(feats, msk, trans, o);
}

// round 8
// speedup vs baseline: 1.2517x; 1.1248x over previous
#include <cuda_runtime.h>
#include <cuda_bf16.h>

// CRF forward, scaled-probability domain, f32x2-packed, stall-free prefetch.
//
//   feats      : (512, 1024, 32) f32
//   mask       : (512, 1024)     f32  (0/1 semantics)
//   transition : (32, 32)        f32
//   out        : (1024,)         f32
//
// alpha_t[j] = feat[t,b,j] + logsumexp_i(alpha_{t-1}[i] + T[j,i])
// p = exp(alpha - M), E = exp(T):  q = E p ;  p' = q*(m*ef) + p*(1-m)
//
// Warp g packs batches {2g, 2g+1} into the halves of 64-bit f32x2 regs;
// lane = tag. One step = 16 broadcast LDS.128 + 32 fma.rn.f32x2 (+tree/tail).
//
// CRITICAL FIX vs R4-R6: the prefetch ring holds RAW feats/mask (no dependent
// op at load time). em/om for step t+1 are computed at step t from ring
// entries loaded >=7 steps ago, so neither the LDG (~250-580 cyc) nor the
// MUFU (16 cyc) latency ever lands on the recurrence chain.
//
// Renorm: delayed-apply, period 4 (butterfly/log/rcp off-chain, single
// packed MUL on-chain). 8-step unapplied growth <= 2^110 < fp32 max.
//
// SMEM: single-buffered p per warp; within-warp LDS-before-STS program order
// makes it safe without __syncwarp (validated R6, rel_err 1.9e-7).
//
// 512 warps = 128 blocks x 128 threads -> 1 warp/SMSP on 128 SMs.

#define SEQ   512
#define BATCH 1024
#define TAGS  32
#define START_TAG 30
#define END_TAG   31
#define WPB   4
#define TPB   128
#define NBLOCKS 128

typedef unsigned long long u64;

__device__ __forceinline__ u64 pack2(float lo, float hi) {
    u64 r; asm("mov.b64 %0, {%1, %2};" : "=l"(r) : "f"(lo), "f"(hi)); return r;
}
__device__ __forceinline__ void unpack2(u64 v, float& lo, float& hi) {
    asm("mov.b64 {%0, %1}, %2;" : "=f"(lo), "=f"(hi) : "l"(v));
}
__device__ __forceinline__ u64 fma2(u64 a, u64 b, u64 c) {
    u64 r; asm("fma.rn.f32x2 %0, %1, %2, %3;" : "=l"(r) : "l"(a), "l"(b), "l"(c)); return r;
}
__device__ __forceinline__ u64 add2(u64 a, u64 b) {
    u64 r; asm("add.rn.f32x2 %0, %1, %2;" : "=l"(r) : "l"(a), "l"(b)); return r;
}
__device__ __forceinline__ u64 mul2(u64 a, u64 b) {
    u64 r; asm("mul.rn.f32x2 %0, %1, %2;" : "=l"(r) : "l"(a), "l"(b)); return r;
}

__global__ __launch_bounds__(TPB, 1)
void crf_fwd_kernel(const float* __restrict__ feats,
                    const float* __restrict__ mask,
                    const float* __restrict__ trans,
                    float* __restrict__ out)
{
    const int j  = threadIdx.x & 31;        // tag
    const int w  = threadIdx.x >> 5;        // warp in block
    const int g  = blockIdx.x * WPB + w;    // global warp id
    const int b0 = 2 * g;                   // batches b0 (lo half), b0+1 (hi)

    __shared__ __align__(16) u64 sp[WPB][TAGS];   // packed p, single buffer

    // ---- E row j, duplicated into both halves ----------------------------
    u64 e2[TAGS];
#pragma unroll
    for (int i = 0; i < TAGS; ++i) {
        const float e = __expf(trans[j * TAGS + i]);
        e2[i] = pack2(e, e);
    }
    const float eEnd = __expf(trans[END_TAG * TAGS + j]);

    // ---- init ------------------------------------------------------------
    const float pinit = (j == START_TAG) ? 1.0f : 0.0f;
    u64 p2 = pack2(pinit, pinit);
    float M0 = 0.0f, M1 = 0.0f;
    u64 pinv2 = pack2(1.0f, 1.0f);          // pending delayed scale
    sp[w][j] = p2;

    // ---- RAW prefetch rings, 8 steps ahead (no dependent ops at load) ----
    const int fbA = b0 * TAGS + j;          // batch b0 feat index
    const int fbB = fbA + TAGS;             // batch b0+1
    const float2* __restrict__ MK2 = reinterpret_cast<const float2*>(mask);

    float  fA[8], fB[8];
    float2 mv[8];
#pragma unroll
    for (int u = 0; u < 8; ++u) {
        fA[u] = feats[u * (BATCH * TAGS) + fbA];
        fB[u] = feats[u * (BATCH * TAGS) + fbB];
        mv[u] = MK2[u * (BATCH / 2) + g];
    }

    // em/om for step 0 (prologue: one unavoidable LDG wait)
    u64 em2 = pack2(mv[0].x * __expf(fA[0]), mv[0].y * __expf(fB[0]));
    u64 om2 = pack2(1.0f - mv[0].x, 1.0f - mv[0].y);
    __syncwarp();                            // initial sp stores visible

    // ---- main recurrence -------------------------------------------------
    for (int blk = 0; blk < SEQ / 8; ++blk) {
        const int t0 = blk * 8;

#pragma unroll
        for (int u = 0; u < 8; ++u) {
            const u64 emc = em2, omc = om2;  // consume (prepared last step)

            // prepare em/om for step t+1 from ring slot (u+1)&7
            // (loaded >=7 steps ago -> data long resident; MUFU off-chain)
            {
                const int un = (u + 1) & 7;
                const float2 mn = mv[un];
                em2 = pack2(mn.x * __expf(fA[un]), mn.y * __expf(fB[un]));
                om2 = pack2(1.0f - mn.x, 1.0f - mn.y);
            }

            // prefetch step t+8 into slot u (pure LDG, consumer 8 steps away)
            {
                const int tp = (t0 + 8 + u) & (SEQ - 1);
                fA[u] = feats[tp * (BATCH * TAGS) + fbA];
                fB[u] = feats[tp * (BATCH * TAGS) + fbB];
                mv[u] = MK2[tp * (BATCH / 2) + g];
            }

            asm volatile("" ::: "memory");   // keep prior STS before LDS

            // q2[j] = sum_i e2[i]*p2[i] : 16 broadcast LDS.128, 8 accums
            const ulonglong2* __restrict__ src =
                reinterpret_cast<const ulonglong2*>(sp[w]);
            u64 a0 = 0, a1 = 0, a2 = 0, a3 = 0, a4 = 0, a5 = 0, a6 = 0, a7 = 0;
#pragma unroll
            for (int h = 0; h < 4; ++h) {
                const ulonglong2 v0 = src[4 * h + 0];
                const ulonglong2 v1 = src[4 * h + 1];
                const ulonglong2 v2 = src[4 * h + 2];
                const ulonglong2 v3 = src[4 * h + 3];
                a0 = fma2(e2[8 * h + 0], v0.x, a0);
                a1 = fma2(e2[8 * h + 1], v0.y, a1);
                a2 = fma2(e2[8 * h + 2], v1.x, a2);
                a3 = fma2(e2[8 * h + 3], v1.y, a3);
                a4 = fma2(e2[8 * h + 4], v2.x, a4);
                a5 = fma2(e2[8 * h + 5], v2.y, a5);
                a6 = fma2(e2[8 * h + 6], v3.x, a6);
                a7 = fma2(e2[8 * h + 7], v3.y, a7);
            }
            const u64 q2 = add2(add2(add2(a0, a1), add2(a2, a3)),
                                add2(add2(a4, a5), add2(a6, a7)));

            // p' = q*em + p*om   (p*om computable while matvec runs)
            p2 = fma2(q2, emc, mul2(p2, omc));

            // ---- delayed renorm, period 4 --------------------------------
            if ((u & 3) == 3) {
                p2 = mul2(p2, pinv2);        // apply PREVIOUS scale (on-chain)
                float sx, sy; unpack2(p2, sx, sy);   // snapshot (off-chain)
#pragma unroll
                for (int off = 16; off > 0; off >>= 1) {
                    sx = fmaxf(sx, __shfl_xor_sync(0xffffffffu, sx, off));
                    sy = fmaxf(sy, __shfl_xor_sync(0xffffffffu, sy, off));
                }
                M0 += __logf(sx);
                M1 += __logf(sy);
                pinv2 = pack2(__frcp_rn(sx), __frcp_rn(sy));
            }

            sp[w][j] = p2;                   // publish for next step
        }
    }

    // ---- epilogue --------------------------------------------------------
    p2 = mul2(p2, pinv2);
    float px, py; unpack2(p2, px, py);
    float ax = px * eEnd;
    float ay = py * eEnd;
#pragma unroll
    for (int off = 16; off > 0; off >>= 1) {
        ax += __shfl_xor_sync(0xffffffffu, ax, off);
        ay += __shfl_xor_sync(0xffffffffu, ay, off);
    }
    if (j == 0) {
        out[b0]     = M0 + __logf(ax);
        out[b0 + 1] = M1 + __logf(ay);
    }
}

extern "C" void kernel_launch(void* const* d_in, const int* in_sizes, int n_in,
                              void* d_out, int out_size)
{
    const float* feats = (const float*)d_in[0];
    const float* msk   = (const float*)d_in[1];
    const float* trans = (const float*)d_in[2];
    float*       o     = (float*)d_out;

    crf_fwd_kernel<<<NBLOCKS, TPB>>>(feats, msk, trans, o);
}